// round 6
// baseline (speedup 1.0000x reference)
#include <cuda_runtime.h>
#include <cstdint>

// Problem constants
#define B_  128
#define C1_ 128
#define C2_ 14
#define S_  14
#define H_  256

#define THREADS 224   // 7 warps

// Shared memory word layout (floats):
//  x slices: 2 buffers of [32 j][14 n][17]   (slots 0,15 zero-pad)
//  Bsp:      2 buffers of [3 i][4 step][32 n][4 t] float2 pairs (k, k+4)
//  Cs:       [224 r][36]  -- aliased onto x region after mainloop
#define XBUF_W   (32 * 14 * 17)            // 7616 words
#define BS_W     (2 * XBUF_W)              // 15232
#define BS_JBUF  (3 * 4 * 32 * 8)          // 3072 words (12 KB)
#define CS_STRIDE 36
#define SMEM_WORDS (BS_W + 2 * BS_JBUF)    // 21376 words = 85504 B

__device__ __forceinline__ float tf32r(float v) {
    float r;
    asm("cvt.rna.tf32.f32 %0, %1;" : "=f"(r) : "f"(v));
    return r;
}

__device__ __forceinline__ void mma_tf32(float c[4],
                                         unsigned a0, unsigned a1, unsigned a2, unsigned a3,
                                         unsigned b0, unsigned b1) {
    asm volatile(
        "mma.sync.aligned.m16n8k8.row.col.f32.tf32.tf32.f32 "
        "{%0,%1,%2,%3}, {%4,%5,%6,%7}, {%8,%9}, {%0,%1,%2,%3};"
        : "+f"(c[0]), "+f"(c[1]), "+f"(c[2]), "+f"(c[3])
        : "r"(a0), "r"(a1), "r"(a2), "r"(a3), "r"(b0), "r"(b1));
}

// ---------------------------------------------------------------------------
// Fused kernel. Block = (b, 32-h chunk). GEMM M=224 rows r=(m*14+n), N=32,
// K=384=(i,j) on tf32 MMA. Mainloop: 4 j-blocks, ONE sync per j-block; per
// j-block all 3 i-chunks of B are staged as k-paired float2 (conflict-free
// LDS.64 fragment loads). Fused roll epilogue from C tile in smem.
// ---------------------------------------------------------------------------
__global__ void __launch_bounds__(THREADS, 2) fused_kernel(
    const float* __restrict__ x,       // (B, C1*C2, S)
    const float* __restrict__ w0,      // (H, 2)
    const float* __restrict__ w1,      // (C1, 3, H)
    const int*   __restrict__ shift_p, // scalar (may be null -> 1)
    float*       __restrict__ out)     // (B, H, C2, S)
{
    extern __shared__ float sm[];

    const int bid = blockIdx.x;
    const int b   = bid >> 3;
    const int h0  = (bid & 7) * 32;

    const int tid  = threadIdx.x;
    const int w    = tid >> 5;
    const int lane = tid & 31;
    const int t    = lane & 3;
    const int q    = lane >> 2;

    // ---- Zero static pad slots of BOTH x buffers ----
    for (int p = tid; p < 2 * 32 * 14; p += THREADS) {
        int buf = p >= 448;
        int r   = p - buf * 448;
        int j   = r / 14, n = r - (r / 14) * 14;
        int base = buf * XBUF_W + j * 238 + n * 17;
        sm[base + 0]  = 0.0f;
        sm[base + 15] = 0.0f;
    }

    const float* xb = x + (size_t)b * (C1_ * C2_ * S_);

    // ---- x-slice staging (32 j rows = 1568 float4, 7/thread) ----
    float4 xr[7];
    auto ldg_x = [&](int jb) {
#pragma unroll
        for (int k = 0; k < 7; ++k) {
            int idx4 = tid + k * THREADS;
            int j = idx4 / 49, f = idx4 - j * 49;
            xr[k] = __ldg(reinterpret_cast<const float4*>(xb) + (jb * 32 + j) * 49 + f);
        }
    };
    auto sts_x = [&](int buf) {
#pragma unroll
        for (int k = 0; k < 7; ++k) {
            int idx4 = tid + k * THREADS;
            int j = idx4 / 49, f = idx4 - j * 49;
            int e = f * 4;
            float v[4] = {xr[k].x, xr[k].y, xr[k].z, xr[k].w};
#pragma unroll
            for (int l = 0; l < 4; ++l) {
                int ee = e + l;
                int n = ee / 14, m = ee - n * 14;
                sm[buf * XBUF_W + j * 238 + n * 17 + m + 1] = tf32r(v[l]);
            }
        }
    };

    // ---- B staging: whole j-block (3 i) as k-pairs. 1536 pairs, 7/thread ----
    float bv0[7], bv1[7];
    auto ldg_b = [&](int jb) {
#pragma unroll
        for (int k = 0; k < 7; ++k) {
            int p = tid + k * THREADS;
            if (p < 1536) {
                int n    = p & 31;
                int tt   = (p >> 5) & 3;
                int step = (p >> 7) & 3;
                int i    = p >> 9;               // 0..2
                int jl   = 8 * step + tt;
                const float* base = w1 + (size_t)((jb * 32 + jl) * 3 + i) * H_ + h0 + n;
                bv0[k] = __ldg(base);
                bv1[k] = __ldg(base + 4 * 3 * H_);   // j+4
            }
        }
    };
    auto sts_b = [&](int buf) {
#pragma unroll
        for (int k = 0; k < 7; ++k) {
            int p = tid + k * THREADS;
            if (p < 1536) {
                int n    = p & 31;
                int tt   = (p >> 5) & 3;
                int step = (p >> 7) & 3;
                int i    = p >> 9;
                int wo = BS_W + buf * BS_JBUF + ((i * 4 + step) * 32 + n) * 8 + 2 * tt;
                *reinterpret_cast<float2*>(&sm[wo]) = make_float2(tf32r(bv0[k]), tf32r(bv1[k]));
            }
        }
    };

    // ---- Per-thread A-row offsets (r = 32w + q + 8u), clamp pad rows ----
    int rw[4];
#pragma unroll
    for (int u = 0; u < 4; ++u) {
        int r  = 32 * w + q + 8 * u;
        int mr = r / 14;
        int nr = r - mr * 14;
        if (mr > 13) mr = 13;
        rw[u] = nr * 17 + mr;
    }

    // ---- Prologue ----
    ldg_x(0);
    ldg_b(0);
    sts_x(0);
    sts_b(0);
    __syncthreads();

    float cf[8][4];
#pragma unroll
    for (int f = 0; f < 8; ++f)
#pragma unroll
        for (int r = 0; r < 4; ++r) cf[f][r] = 0.0f;

    // ---- Main loop: 4 j-blocks, one sync each ----
#pragma unroll 1
    for (int jb = 0; jb < 4; ++jb) {
        const int xw = (jb & 1) * XBUF_W;
        const int bw = BS_W + (jb & 1) * BS_JBUF;

        if (jb < 3) { ldg_x(jb + 1); ldg_b(jb + 1); }

#pragma unroll
        for (int ii = 0; ii < 3; ++ii) {
#pragma unroll
            for (int step = 0; step < 4; ++step) {
                const int jloc = 8 * step + t;
                const int ab0 = xw + jloc * 238 + ii;
                const int ab4 = ab0 + 4 * 238;

                unsigned a[2][4];
#pragma unroll
                for (int fm = 0; fm < 2; ++fm) {
                    a[fm][0] = __float_as_uint(sm[ab0 + rw[2 * fm]]);
                    a[fm][1] = __float_as_uint(sm[ab0 + rw[2 * fm + 1]]);
                    a[fm][2] = __float_as_uint(sm[ab4 + rw[2 * fm]]);
                    a[fm][3] = __float_as_uint(sm[ab4 + rw[2 * fm + 1]]);
                }
                const int bbase = bw + (ii * 4 + step) * 256 + 2 * t;
#pragma unroll
                for (int fn = 0; fn < 4; ++fn) {
                    float2 bp = *reinterpret_cast<const float2*>(
                        &sm[bbase + (8 * fn + q) * 8]);
                    unsigned b0 = __float_as_uint(bp.x);
                    unsigned b1 = __float_as_uint(bp.y);
                    mma_tf32(cf[fn],     a[0][0], a[0][1], a[0][2], a[0][3], b0, b1);
                    mma_tf32(cf[4 + fn], a[1][0], a[1][1], a[1][2], a[1][3], b0, b1);
                }
            }
        }

        if (jb < 3) { sts_x((jb + 1) & 1); sts_b((jb + 1) & 1); }
        __syncthreads();
    }

    // ---- Write C tile to smem (aliases x region) ----
#pragma unroll
    for (int fm = 0; fm < 2; ++fm) {
#pragma unroll
        for (int fn = 0; fn < 4; ++fn) {
            const float* cc = cf[fm * 4 + fn];
            int r1  = 32 * w + 16 * fm + q;
            int r2  = r1 + 8;
            int col = 8 * fn + 2 * t;
            *reinterpret_cast<float2*>(&sm[r1 * CS_STRIDE + col]) = make_float2(cc[0], cc[1]);
            *reinterpret_cast<float2*>(&sm[r2 * CS_STRIDE + col]) = make_float2(cc[2], cc[3]);
        }
    }
    __syncthreads();

    // ---- Fused roll epilogue ----
    const int s   = shift_p ? shift_p[0] : 1;
    const int s28 = ((s % 28) + 28) % 28;
    const int s14 = ((s % 14) + 14) % 14;

#pragma unroll
    for (int it = 0; it < 2; ++it) {
        int idx = it * THREADS + tid;   // 0..447
        int h_l = idx & 31;
        int nb  = idx >> 5;             // 0..13

        float2 w0p = __ldg(reinterpret_cast<const float2*>(w0) + (h0 + h_l));

        int n2[2];
        float wv[2];
#pragma unroll
        for (int e = 0; e < 2; ++e) {
            int g  = (nb * 2 + e - s28 + 56) % 28;
            int n1 = g >> 1;
            int e1 = g & 1;
            n2[e]  = (n1 - s14 + 14) % 14;
            wv[e]  = e1 ? w0p.y : w0p.x;
        }

        float* orow = out + (size_t)(b * H_ + h0 + h_l) * (C2_ * S_) + nb * S_;
#pragma unroll
        for (int mm = 0; mm < 7; ++mm) {
            int m0 = 2 * mm, m1 = 2 * mm + 1;
            float v0 = sm[(m0 * 14 + n2[0]) * CS_STRIDE + h_l] * wv[0]
                     + sm[(m0 * 14 + n2[1]) * CS_STRIDE + h_l] * wv[1];
            float v1 = sm[(m1 * 14 + n2[0]) * CS_STRIDE + h_l] * wv[0]
                     + sm[(m1 * 14 + n2[1]) * CS_STRIDE + h_l] * wv[1];
            *reinterpret_cast<float2*>(orow + m0) = make_float2(v0, v1);
        }
    }
}

// ---------------------------------------------------------------------------
extern "C" void kernel_launch(void* const* d_in, const int* in_sizes, int n_in,
                              void* d_out, int out_size)
{
    const float* x     = (const float*)d_in[0];
    const float* w0    = (const float*)d_in[1];
    const float* w1    = (const float*)d_in[2];
    const int*   shift = (n_in >= 4) ? (const int*)d_in[3] : nullptr;

    (void)in_sizes; (void)out_size;

    cudaFuncSetAttribute(fused_kernel,
                         cudaFuncAttributeMaxDynamicSharedMemorySize,
                         SMEM_WORDS * 4);

    fused_kernel<<<B_ * 8, THREADS, SMEM_WORDS * 4>>>(x, w0, w1, shift, (float*)d_out);
}

// round 7
// speedup vs baseline: 1.0232x; 1.0232x over previous
#include <cuda_runtime.h>
#include <cstdint>

// Problem constants
#define B_  128
#define C1_ 128
#define C2_ 14
#define S_  14
#define H_  256

#define THREADS 224   // 7 warps

// Shared memory word layout (floats):
//  x windows: 2 buffers of [mp:16][n:14][33]  (j stored PERMUTED: slot
//             p(j)=8*(j&3)+(j>>2); mp=0,15 are zero pad)
//  Bs:        2 buffers of [step:4][n:32][t:4] float2 pairs (k=t, k=t+4)
//  Cs:        [224 r][36] -- aliased onto x region after mainloop
#define XBUF_W   (16 * 14 * 33)            // 7392 words
#define BS_W     (2 * XBUF_W)              // 14784
#define BS_BUF   1024                      // words per B chunk buffer
#define CS_STRIDE 36
#define SMEM_WORDS (BS_W + 2 * BS_BUF)     // 16832 words = 67328 B

__device__ __forceinline__ float tf32r(float v) {
    float r;
    asm("cvt.rna.tf32.f32 %0, %1;" : "=f"(r) : "f"(v));
    return r;
}

__device__ __forceinline__ void mma_tf32(float c[4],
                                         unsigned a0, unsigned a1, unsigned a2, unsigned a3,
                                         unsigned b0, unsigned b1) {
    asm volatile(
        "mma.sync.aligned.m16n8k8.row.col.f32.tf32.tf32.f32 "
        "{%0,%1,%2,%3}, {%4,%5,%6,%7}, {%8,%9}, {%0,%1,%2,%3};"
        : "+f"(c[0]), "+f"(c[1]), "+f"(c[2]), "+f"(c[3])
        : "r"(a0), "r"(a1), "r"(a2), "r"(a3), "r"(b0), "r"(b1));
}

// ---------------------------------------------------------------------------
// Fused kernel. Block = (b, 32-h chunk). GEMM M=224 rows r=(m*14+n), N=32,
// K=384=(i,j) on tf32 MMA. x window transposed+j-permuted so all A fragment
// LDS are bank-conflict-free with compile-time immediate offsets. B k-paired
// (LDS.64, conflict-free). Per-chunk double-buffered staging. Fused roll
// epilogue from C tile in smem.
// ---------------------------------------------------------------------------
__global__ void __launch_bounds__(THREADS, 2) fused_kernel(
    const float* __restrict__ x,       // (B, C1*C2, S)
    const float* __restrict__ w0,      // (H, 2)
    const float* __restrict__ w1,      // (C1, 3, H)
    const int*   __restrict__ shift_p, // scalar (may be null -> 1)
    float*       __restrict__ out)     // (B, H, C2, S)
{
    extern __shared__ float sm[];

    const int bid = blockIdx.x;
    const int b   = bid >> 3;
    const int h0  = (bid & 7) * 32;

    const int tid  = threadIdx.x;
    const int w    = tid >> 5;
    const int lane = tid & 31;
    const int t    = lane & 3;
    const int q    = lane >> 2;

    // ---- Zero pad planes mp=0 and mp=15 of BOTH x buffers ----
    for (int p = tid; p < 2 * 14 * 32; p += THREADS) {
        int buf = p >= 448;
        int rr  = p - buf * 448;
        int n   = rr >> 5;
        int jj  = rr & 31;
        int base = buf * XBUF_W + n * 33 + jj;
        sm[base + 0 * 462]  = 0.0f;
        sm[base + 15 * 462] = 0.0f;
    }

    const float* xb = x + (size_t)b * (C1_ * C2_ * S_);

    // ---- x-window staging (32 j rows = 1568 float4, 7/thread) ----
    float4 xr[7];
    auto ldg_x = [&](int jb) {
#pragma unroll
        for (int k = 0; k < 7; ++k) {
            int idx4 = tid + k * THREADS;
            int j = idx4 / 49, f = idx4 - j * 49;
            xr[k] = __ldg(reinterpret_cast<const float4*>(xb) + (jb * 32 + j) * 49 + f);
        }
    };
    auto sts_x = [&](int buf) {
#pragma unroll
        for (int k = 0; k < 7; ++k) {
            int idx4 = tid + k * THREADS;
            int j = idx4 / 49, f = idx4 - j * 49;
            int pj = 8 * (j & 3) + (j >> 2);      // permuted j slot
            int e = f * 4;
            float v[4] = {xr[k].x, xr[k].y, xr[k].z, xr[k].w};
#pragma unroll
            for (int l = 0; l < 4; ++l) {
                int ee = e + l;
                int n = ee / 14, m = ee - n * 14;
                sm[buf * XBUF_W + (m + 1) * 462 + n * 33 + pj] = tf32r(v[l]);
            }
        }
    };

    // ---- B chunk staging: 512 k-pairs (3/thread) ----
    float bv0[3], bv1[3];
    auto ldg_b = [&](int jb, int i) {
#pragma unroll
        for (int k = 0; k < 3; ++k) {
            int p = tid + k * THREADS;
            if (p < 512) {
                int n    = p & 31;
                int tt   = (p >> 5) & 3;
                int step = p >> 7;
                int jl   = 8 * step + tt;
                const float* base = w1 + (size_t)((jb * 32 + jl) * 3 + i) * H_ + h0 + n;
                bv0[k] = __ldg(base);
                bv1[k] = __ldg(base + 4 * 3 * H_);   // j+4 partner
            }
        }
    };
    auto sts_b = [&](int buf) {
#pragma unroll
        for (int k = 0; k < 3; ++k) {
            int p = tid + k * THREADS;
            if (p < 512) {
                int n    = p & 31;
                int tt   = (p >> 5) & 3;
                int step = p >> 7;
                int wo = BS_W + buf * BS_BUF + step * 256 + n * 8 + 2 * tt;
                *reinterpret_cast<float2*>(&sm[wo]) = make_float2(tf32r(bv0[k]), tf32r(bv1[k]));
            }
        }
    };

    // ---- Per-thread A base offsets: pa[u] = mr*462 + nr*33 + 8t ----
    int pa[4];
#pragma unroll
    for (int u = 0; u < 4; ++u) {
        int r  = 32 * w + q + 8 * u;
        int mr = r / 14;
        int nr = r - mr * 14;
        if (mr > 13) mr = 13;     // pad rows -> harmless valid garbage
        pa[u] = mr * 462 + nr * 33 + 8 * t;
    }

    // ---- Prologue ----
    ldg_x(0);
    ldg_b(0, 0);
    sts_x(0);
    sts_b(0);
    __syncthreads();

    float cf[8][4];
#pragma unroll
    for (int f = 0; f < 8; ++f)
#pragma unroll
        for (int r = 0; r < 4; ++r) cf[f][r] = 0.0f;

    const int pbq = q * 8 + 2 * t;   // B fragment base (lane part)

    // ---- Main loop: 4 j-blocks x 3 i-chunks (ii unrolled -> immediates) ----
#pragma unroll 1
    for (int jb = 0; jb < 4; ++jb) {
        const int xw = (jb & 1) * XBUF_W;
        int paw[4];
#pragma unroll
        for (int u = 0; u < 4; ++u) paw[u] = xw + pa[u];

#pragma unroll
        for (int ii = 0; ii < 3; ++ii) {
            // Prefetch next chunk's B; at ii==0 also next j-block's x
            if (ii < 2)              ldg_b(jb, ii + 1);
            else if (jb < 3)         ldg_b(jb + 1, 0);
            if (ii == 0 && jb < 3)   ldg_x(jb + 1);

            const int bw = BS_W + ((jb + ii) & 1) * BS_BUF + pbq;

#pragma unroll
            for (int step = 0; step < 4; ++step) {
                const int aoff = ii * 462 + 2 * step;   // compile-time imm

                unsigned a[2][4];
#pragma unroll
                for (int fm = 0; fm < 2; ++fm) {
                    a[fm][0] = __float_as_uint(sm[paw[2 * fm]     + aoff]);
                    a[fm][1] = __float_as_uint(sm[paw[2 * fm + 1] + aoff]);
                    a[fm][2] = __float_as_uint(sm[paw[2 * fm]     + aoff + 1]);
                    a[fm][3] = __float_as_uint(sm[paw[2 * fm + 1] + aoff + 1]);
                }
#pragma unroll
                for (int fn = 0; fn < 4; ++fn) {
                    float2 bp = *reinterpret_cast<const float2*>(
                        &sm[bw + step * 256 + fn * 64]);
                    unsigned b0 = __float_as_uint(bp.x);
                    unsigned b1 = __float_as_uint(bp.y);
                    mma_tf32(cf[fn],     a[0][0], a[0][1], a[0][2], a[0][3], b0, b1);
                    mma_tf32(cf[4 + fn], a[1][0], a[1][1], a[1][2], a[1][3], b0, b1);
                }
            }

            // Publish staged data for the next chunk
            if (ii == 2 && jb < 3) sts_x((jb + 1) & 1);
            if (!(ii == 2 && jb == 3)) sts_b((jb + ii + 1) & 1);
            __syncthreads();
        }
    }

    // ---- Write C tile to smem (aliases x region) ----
#pragma unroll
    for (int fm = 0; fm < 2; ++fm) {
#pragma unroll
        for (int fn = 0; fn < 4; ++fn) {
            const float* cc = cf[fm * 4 + fn];
            int r1  = 32 * w + 16 * fm + q;
            int r2  = r1 + 8;
            int col = 8 * fn + 2 * t;
            *reinterpret_cast<float2*>(&sm[r1 * CS_STRIDE + col]) = make_float2(cc[0], cc[1]);
            *reinterpret_cast<float2*>(&sm[r2 * CS_STRIDE + col]) = make_float2(cc[2], cc[3]);
        }
    }
    __syncthreads();

    // ---- Fused roll epilogue ----
    const int s   = shift_p ? shift_p[0] : 1;
    const int s28 = ((s % 28) + 28) % 28;
    const int s14 = ((s % 14) + 14) % 14;

#pragma unroll
    for (int it = 0; it < 2; ++it) {
        int idx = it * THREADS + tid;   // 0..447
        int h_l = idx & 31;
        int nb  = idx >> 5;             // 0..13

        float2 w0p = __ldg(reinterpret_cast<const float2*>(w0) + (h0 + h_l));

        int n2[2];
        float wv[2];
#pragma unroll
        for (int e = 0; e < 2; ++e) {
            int g  = (nb * 2 + e - s28 + 56) % 28;
            int n1 = g >> 1;
            int e1 = g & 1;
            n2[e]  = (n1 - s14 + 14) % 14;
            wv[e]  = e1 ? w0p.y : w0p.x;
        }

        float* orow = out + (size_t)(b * H_ + h0 + h_l) * (C2_ * S_) + nb * S_;
#pragma unroll
        for (int mm = 0; mm < 7; ++mm) {
            int m0 = 2 * mm, m1 = 2 * mm + 1;
            float v0 = sm[(m0 * 14 + n2[0]) * CS_STRIDE + h_l] * wv[0]
                     + sm[(m0 * 14 + n2[1]) * CS_STRIDE + h_l] * wv[1];
            float v1 = sm[(m1 * 14 + n2[0]) * CS_STRIDE + h_l] * wv[0]
                     + sm[(m1 * 14 + n2[1]) * CS_STRIDE + h_l] * wv[1];
            *reinterpret_cast<float2*>(orow + m0) = make_float2(v0, v1);
        }
    }
}

// ---------------------------------------------------------------------------
extern "C" void kernel_launch(void* const* d_in, const int* in_sizes, int n_in,
                              void* d_out, int out_size)
{
    const float* x     = (const float*)d_in[0];
    const float* w0    = (const float*)d_in[1];
    const float* w1    = (const float*)d_in[2];
    const int*   shift = (n_in >= 4) ? (const int*)d_in[3] : nullptr;

    (void)in_sizes; (void)out_size;

    cudaFuncSetAttribute(fused_kernel,
                         cudaFuncAttributeMaxDynamicSharedMemorySize,
                         SMEM_WORDS * 4);

    fused_kernel<<<B_ * 8, THREADS, SMEM_WORDS * 4>>>(x, w0, w1, shift, (float*)d_out);
}